// round 9
// baseline (speedup 1.0000x reference)
#include <cuda_runtime.h>
#include <cuda_bf16.h>
#include <cstdint>

#define NUM_USERS 50000
#define NUM_ITEMS 40000
#define EMB 64
#define NNZ 2000000
#define BATCH 1024

// ---- scratch (static __device__ globals; no allocation allowed) ----
__device__ float         g_WqT[NUM_ITEMS * 128];     // Wq transposed: [item][128]
__device__ __nv_bfloat16 g_Wpb[NUM_ITEMS * EMB];     // Wp in bf16:   [item][64]
__device__ float         g_hsel[BATCH * 128];        // selected-user h accumulators
__device__ int           g_map[NUM_USERS];           // user -> batch slot (validated by back-check)
__device__ __nv_bfloat16 g_zb[BATCH * EMB];          // z in bf16
__device__ float         g_sexp[BATCH];
__device__ float         g_sdot[BATCH];
__device__ float         g_scnt[BATCH];
__device__ float         g_kl;

__device__ __forceinline__ unsigned pack_bf162(float lo, float hi) {
    __nv_bfloat162 t = __floats2bfloat162_rn(lo, hi);
    return *(unsigned*)&t;
}

// ---- 1: fused prep: Wq transpose + Wp->bf16 + zero scratch + user map ----
__global__ void __launch_bounds__(256)
k_prep(const float* __restrict__ Wq, const float* __restrict__ Wp,
       const int* __restrict__ user) {
    __shared__ float tile[32][33];
    int bid = blockIdx.x, tid = threadIdx.x;
    if (bid < 5000) {
        int i0 = (bid % 1250) * 32, k0 = (bid / 1250) * 32;
        int tx = tid & 31, ty = tid >> 5;          // (32,8)
#pragma unroll
        for (int r = 0; r < 32; r += 8)
            tile[ty + r][tx] = Wq[(size_t)(k0 + ty + r) * NUM_ITEMS + i0 + tx];
        __syncthreads();
#pragma unroll
        for (int r = 0; r < 32; r += 8)
            g_WqT[(size_t)(i0 + ty + r) * 128 + k0 + tx] = tile[tx][ty + r];
    } else if (bid < 6250) {
        int i = (bid - 5000) * 256 + tid;          // < 320000 exactly
        const float4* in4 = (const float4*)Wp;
        float4 a = in4[2 * i], b = in4[2 * i + 1];
        uint4 o;
        o.x = pack_bf162(a.x, a.y);
        o.y = pack_bf162(a.z, a.w);
        o.z = pack_bf162(b.x, b.y);
        o.w = pack_bf162(b.z, b.w);
        ((uint4*)g_Wpb)[i] = o;
    } else if (bid < 6762) {
        int i = (bid - 6250) * 256 + tid;          // < 131072 exactly
        g_hsel[i] = 0.f;
    } else {
#pragma unroll
        for (int b = tid; b < BATCH; b += 256) {
            g_sexp[b] = 0.f; g_sdot[b] = 0.f; g_scnt[b] = 0.f;
            g_map[user[b]] = b;                    // racing store; any winner valid
        }
        if (tid == 0) g_kl = 0.f;
    }
}

// ---- 2: scatter kept edges (warp-ballot compaction; map validated by back-check) ----
__global__ void k_edges(const float* __restrict__ vals,
                        const int* __restrict__ rows,
                        const int* __restrict__ cols,
                        const int* __restrict__ user) {
    int idx  = blockIdx.x * blockDim.x + threadIdx.x;
    int lane = threadIdx.x & 31;
    int slot = -1, col = 0;
    float val = 0.f;
    if (idx < NNZ) {
        int r = rows[idx];
        int s = g_map[r];
        if ((unsigned)s < BATCH && __ldg(&user[s]) == r) slot = s;
        col = cols[idx];
        val = vals[idx];
    }
    unsigned m = __ballot_sync(0xFFFFFFFFu, slot >= 0);
    while (m) {
        int j = __ffs(m) - 1; m &= m - 1;
        int   c = __shfl_sync(0xFFFFFFFFu, col, j);
        float v = __shfl_sync(0xFFFFFFFFu, val, j);
        int   s = __shfl_sync(0xFFFFFFFFu, slot, j);
        const float* wr = &g_WqT[(size_t)c * 128];
        float* hr = &g_hsel[s * 128];
#pragma unroll
        for (int k = lane; k < 128; k += 32)
            atomicAdd(&hr[k], v * wr[k]);
    }
}

// ---- 3: reparameterize + KL ----
__global__ void k_z(const float* __restrict__ bq,
                    const float* __restrict__ eps,
                    const int* __restrict__ user) {
    int b = blockIdx.x, k = threadIdx.x;   // 64 threads
    int u = user[b];
    int s = g_map[u];
    float mu = g_hsel[s * 128 + k]      + bq[k];
    float lv = g_hsel[s * 128 + 64 + k] + bq[64 + k];
    float z  = mu + eps[u * EMB + k] * __expf(0.5f * lv);
    g_zb[b * EMB + k] = __float2bfloat16(z);
    float t = 1.f + lv - mu * mu - __expf(lv);
#pragma unroll
    for (int o = 16; o > 0; o >>= 1) t += __shfl_down_sync(0xFFFFFFFFu, t, o);
    __shared__ float sm[2];
    if ((threadIdx.x & 31) == 0) sm[threadIdx.x >> 5] = t;
    __syncthreads();
    if (threadIdx.x == 0) atomicAdd(&g_kl, sm[0] + sm[1]);
}

// ---- 4: fused decoder GEMM (bf16 HMMA) + softmax-stats epilogue ----
// x tile streamed via cp.async (deep MLP) through 2x8KB smem chunks,
// packed to a nibble-byte mask; Wpb tile in smem.
__device__ __forceinline__ void mma16816(float* d, const unsigned* a, const unsigned* b) {
    asm volatile(
        "mma.sync.aligned.m16n8k16.row.col.f32.bf16.bf16.f32 "
        "{%0,%1,%2,%3}, {%4,%5,%6,%7}, {%8,%9}, {%0,%1,%2,%3};\n"
        : "+f"(d[0]), "+f"(d[1]), "+f"(d[2]), "+f"(d[3])
        : "r"(a[0]), "r"(a[1]), "r"(a[2]), "r"(a[3]), "r"(b[0]), "r"(b[1]));
}

__device__ __forceinline__ void cp_async16(void* smem_dst, const void* gsrc, int src_bytes) {
    unsigned saddr = (unsigned)__cvta_generic_to_shared(smem_dst);
    asm volatile("cp.async.cg.shared.global [%0], [%1], 16, %2;\n"
                 :: "r"(saddr), "l"(gsrc), "r"(src_bytes));
}
__device__ __forceinline__ void cp_commit() {
    asm volatile("cp.async.commit_group;\n" ::: "memory");
}
template <int N>
__device__ __forceinline__ void cp_wait() {
    asm volatile("cp.async.wait_group %0;\n" :: "n"(N) : "memory");
}

#define WP_STRIDE 144   // bytes per smem Wp row: 128 data + 16 pad
#define XB_STRIDE 36    // bytes per bitmask row: 32 nibble-bytes + 4 pad

__global__ void __launch_bounds__(256, 3)
k_gemm(const float* __restrict__ bp, const float* __restrict__ x) {
    __shared__ __align__(16) unsigned char sWp[128 * WP_STRIDE];   // 18.0 KB
    __shared__ __align__(16) unsigned char sXb[128 * XB_STRIDE];   //  4.5 KB
    __shared__ __align__(16) float sXraw[2][16 * 128];             // 16.0 KB

    int tid = threadIdx.x;
    int w = tid >> 5, lane = tid & 31;
    int wm = w & 3, wn = w >> 2;                 // 4 warps along M, 2 along N
    int m_blk  = blockIdx.y * 128;
    int m_base = m_blk + wm * 32;                // batch rows (in-range)
    int n_blk  = blockIdx.x * 128;
    int n_base = n_blk + wn * 64;                // item cols (tail-predicated)
    int g = lane >> 2, tg = lane & 3;

    // ---- issue first two x chunks (16 rows x 512B each) via cp.async ----
#define ISSUE_CHUNK(C) do {                                                     \
        _Pragma("unroll")                                                       \
        for (int it = 0; it < 2; it++) {                                        \
            int idx = it * 256 + tid;                                           \
            int row = idx >> 5, seg = idx & 31;                                 \
            int grow = m_blk + (C) * 16 + row;                                  \
            int gcol = n_blk + seg * 4;                                         \
            int ok = (gcol + 3 < NUM_ITEMS) ? 16 : 0;                           \
            cp_async16(&sXraw[(C) & 1][row * 128 + seg * 4],                    \
                       &x[(size_t)grow * NUM_ITEMS + gcol], ok);                \
        }                                                                       \
        cp_commit();                                                            \
    } while (0)

    ISSUE_CHUNK(0);
    ISSUE_CHUNK(1);

    // ---- fill smem Wpb tile: rows n_blk..n_blk+127, uint4-coalesced ----
#pragma unroll
    for (int it = 0; it < 4; it++) {
        int i = it * 256 + tid;                  // 0..1023
        int row = i >> 3, off = i & 7;
        int gr = n_blk + row;
        uint4 v = make_uint4(0u, 0u, 0u, 0u);
        if (gr < NUM_ITEMS) v = *(const uint4*)&g_Wpb[(size_t)gr * 64 + off * 8];
        *(uint4*)&sWp[row * WP_STRIDE + off * 16] = v;
    }

    // ---- A fragments: z tile 32(M) x 64(K), register-resident ----
    unsigned a[2][4][4];
#pragma unroll
    for (int mf = 0; mf < 2; mf++) {
        int r0 = m_base + mf * 16 + g;
#pragma unroll
        for (int kf = 0; kf < 4; kf++) {
            int kb = kf * 16 + tg * 2;
            a[mf][kf][0] = *(const unsigned*)&g_zb[(r0)     * 64 + kb];
            a[mf][kf][1] = *(const unsigned*)&g_zb[(r0 + 8) * 64 + kb];
            a[mf][kf][2] = *(const unsigned*)&g_zb[(r0)     * 64 + kb + 8];
            a[mf][kf][3] = *(const unsigned*)&g_zb[(r0 + 8) * 64 + kb + 8];
        }
    }

    // ---- pipelined: wait chunk, pack to nibble bytes, issue chunk+2 ----
#pragma unroll
    for (int c = 0; c < 8; c++) {
        if (c < 7) cp_wait<1>(); else cp_wait<0>();
        __syncthreads();
        if (tid < 128) {
            int row = tid >> 3, seg0 = (tid & 7) * 4;
            const float* buf = sXraw[c & 1];
            unsigned word = 0;
#pragma unroll
            for (int j = 0; j < 4; j++) {
                float4 v = *(const float4*)&buf[row * 128 + (seg0 + j) * 4];
                unsigned nib = (v.x != 0.f ? 1u : 0u) | (v.y != 0.f ? 2u : 0u)
                             | (v.z != 0.f ? 4u : 0u) | (v.w != 0.f ? 8u : 0u);
                word |= nib << (8 * j);
            }
            *(unsigned*)&sXb[(c * 16 + row) * XB_STRIDE + seg0] = word;
        }
        __syncthreads();
        if (c < 6) {
            switch (c) {                          // compile-time chunk index
                case 0: ISSUE_CHUNK(2); break;
                case 1: ISSUE_CHUNK(3); break;
                case 2: ISSUE_CHUNK(4); break;
                case 3: ISSUE_CHUNK(5); break;
                case 4: ISSUE_CHUNK(6); break;
                default: ISSUE_CHUNK(7); break;
            }
        }
    }
#undef ISSUE_CHUNK

    // ---- main compute: MMA + softmax-stats epilogue, bits from sXb ----
    int bsh = (tg & 1) * 2;                      // bit position within nibble
    float sexp[4] = {0, 0, 0, 0}, sdot[4] = {0, 0, 0, 0}, scnt[4] = {0, 0, 0, 0};

#pragma unroll
    for (int nf = 0; nf < 8; nf++) {
        int rloc = wn * 64 + nf * 8 + g;         // local smem Wp row
        unsigned bf[4][2];
#pragma unroll
        for (int kf = 0; kf < 4; kf++) {
            bf[kf][0] = *(const unsigned*)&sWp[rloc * WP_STRIDE + kf * 32 + tg * 4];
            bf[kf][1] = *(const unsigned*)&sWp[rloc * WP_STRIDE + kf * 32 + tg * 4 + 16];
        }

        float d[2][4] = {{0, 0, 0, 0}, {0, 0, 0, 0}};
#pragma unroll
        for (int mf = 0; mf < 2; mf++)
#pragma unroll
            for (int kf = 0; kf < 4; kf++)
                mma16816(d[mf], a[mf][kf], bf[kf]);

        int c0 = n_base + nf * 8 + tg * 2;
        int bofs = wn * 16 + nf * 2 + (tg >> 1); // nibble-byte index within row
        if (c0 < NUM_ITEMS) {
            float2 bpv = *(const float2*)&bp[c0];
#pragma unroll
            for (int mf = 0; mf < 2; mf++)
#pragma unroll
                for (int h = 0; h < 2; h++) {
                    int li = mf * 2 + h;
                    int lrow = wm * 32 + mf * 16 + h * 8 + g;
                    unsigned byte = sXb[lrow * XB_STRIDE + bofs];
                    float v0f = d[mf][h * 2 + 0] + bpv.x;
                    float v1f = d[mf][h * 2 + 1] + bpv.y;
                    sexp[li] += __expf(v0f) + __expf(v1f);
                    if ((byte >> bsh) & 1)       { sdot[li] += v0f; scnt[li] += 1.f; }
                    if ((byte >> (bsh + 1)) & 1) { sdot[li] += v1f; scnt[li] += 1.f; }
                }
        }
    }

    // reduce across the 4 threads of each group (tg), then atomics per row
#pragma unroll
    for (int li = 0; li < 4; li++) {
        float se = sexp[li], sd = sdot[li], sc = scnt[li];
#pragma unroll
        for (int o = 1; o < 4; o <<= 1) {
            se += __shfl_xor_sync(0xFFFFFFFFu, se, o);
            sd += __shfl_xor_sync(0xFFFFFFFFu, sd, o);
            sc += __shfl_xor_sync(0xFFFFFFFFu, sc, o);
        }
        if (tg == 0) {
            int row = m_base + (li >> 1) * 16 + (li & 1) * 8 + g;
            atomicAdd(&g_sexp[row], se);
            atomicAdd(&g_sdot[row], sd);
            atomicAdd(&g_scnt[row], sc);
        }
    }
}

// ---- 5: final reduction ----
__global__ void k_final(float* __restrict__ out) {
    __shared__ float sm[256];
    float acc = 0.f;
    for (int r = threadIdx.x; r < BATCH; r += 256)
        acc += g_scnt[r] * logf(g_sexp[r]) - g_sdot[r];
    sm[threadIdx.x] = acc;
    __syncthreads();
    for (int o = 128; o > 0; o >>= 1) {
        if (threadIdx.x < o) sm[threadIdx.x] += sm[threadIdx.x + o];
        __syncthreads();
    }
    if (threadIdx.x == 0) {
        out[0] = sm[0] / (float)BATCH;
        out[1] = -0.5f * g_kl / (float)BATCH;
    }
}

extern "C" void kernel_launch(void* const* d_in, const int* in_sizes, int n_in,
                              void* d_out, int out_size) {
    const float* graph_vals = (const float*)d_in[0];
    const float* Wq         = (const float*)d_in[1];
    const float* bq         = (const float*)d_in[2];
    const float* Wp         = (const float*)d_in[3];
    const float* bp         = (const float*)d_in[4];
    const float* x          = (const float*)d_in[5];
    const float* eps        = (const float*)d_in[6];
    const int*   graph_rows = (const int*)d_in[7];
    const int*   graph_cols = (const int*)d_in[8];
    const int*   user       = (const int*)d_in[9];
    float* out = (float*)d_out;

    k_prep<<<6763, 256>>>(Wq, Wp, user);
    k_edges<<<(NNZ + 255) / 256, 256>>>(graph_vals, graph_rows, graph_cols, user);
    k_z<<<BATCH, 64>>>(bq, eps, user);
    {
        dim3 grid((NUM_ITEMS + 127) / 128, BATCH / 128);
        k_gemm<<<grid, 256>>>(bp, x);
    }
    k_final<<<1, 256>>>(out);
}

// round 10
// speedup vs baseline: 1.2548x; 1.2548x over previous
#include <cuda_runtime.h>
#include <cuda_bf16.h>
#include <cstdint>

#define NUM_USERS 50000
#define NUM_ITEMS 40000
#define EMB 64
#define NNZ 2000000
#define BATCH 1024

// ---- scratch (static __device__ globals; no allocation allowed) ----
__device__ float         g_WqT[NUM_ITEMS * 128];     // Wq transposed: [item][128]
__device__ __nv_bfloat16 g_Wpb[NUM_ITEMS * EMB];     // Wp in bf16:   [item][64]
__device__ float         g_hsel[BATCH * 128];        // selected-user h accumulators
__device__ int           g_map[NUM_USERS];           // user -> batch slot (validated by back-check)
__device__ __nv_bfloat16 g_zb[BATCH * EMB];          // z in bf16
__device__ float         g_sexp[BATCH];
__device__ float         g_sdot[BATCH];
__device__ float         g_scnt[BATCH];
__device__ float         g_kl;

__device__ __forceinline__ unsigned pack_bf162(float lo, float hi) {
    __nv_bfloat162 t = __floats2bfloat162_rn(lo, hi);
    return *(unsigned*)&t;
}

// ---- 1: fused prep: Wq transpose + Wp->bf16 + zero scratch + user map ----
__global__ void __launch_bounds__(256)
k_prep(const float* __restrict__ Wq, const float* __restrict__ Wp,
       const int* __restrict__ user) {
    __shared__ float tile[32][33];
    int bid = blockIdx.x, tid = threadIdx.x;
    if (bid < 5000) {
        int i0 = (bid % 1250) * 32, k0 = (bid / 1250) * 32;
        int tx = tid & 31, ty = tid >> 5;          // (32,8)
#pragma unroll
        for (int r = 0; r < 32; r += 8)
            tile[ty + r][tx] = Wq[(size_t)(k0 + ty + r) * NUM_ITEMS + i0 + tx];
        __syncthreads();
#pragma unroll
        for (int r = 0; r < 32; r += 8)
            g_WqT[(size_t)(i0 + ty + r) * 128 + k0 + tx] = tile[tx][ty + r];
    } else if (bid < 6250) {
        int i = (bid - 5000) * 256 + tid;          // < 320000 exactly
        const float4* in4 = (const float4*)Wp;
        float4 a = in4[2 * i], b = in4[2 * i + 1];
        uint4 o;
        o.x = pack_bf162(a.x, a.y);
        o.y = pack_bf162(a.z, a.w);
        o.z = pack_bf162(b.x, b.y);
        o.w = pack_bf162(b.z, b.w);
        ((uint4*)g_Wpb)[i] = o;
    } else if (bid < 6762) {
        int i = (bid - 6250) * 256 + tid;          // < 131072 exactly
        g_hsel[i] = 0.f;
    } else {
#pragma unroll
        for (int b = tid; b < BATCH; b += 256) {
            g_sexp[b] = 0.f; g_sdot[b] = 0.f; g_scnt[b] = 0.f;
            g_map[user[b]] = b;                    // racing store; any winner valid
        }
        if (tid == 0) g_kl = 0.f;
    }
}

// ---- 2: scatter kept edges (warp-ballot compaction; map validated by back-check) ----
__global__ void k_edges(const float* __restrict__ vals,
                        const int* __restrict__ rows,
                        const int* __restrict__ cols,
                        const int* __restrict__ user) {
    int idx  = blockIdx.x * blockDim.x + threadIdx.x;
    int lane = threadIdx.x & 31;
    int slot = -1, col = 0;
    float val = 0.f;
    if (idx < NNZ) {
        int r = rows[idx];
        int s = g_map[r];
        if ((unsigned)s < BATCH && __ldg(&user[s]) == r) slot = s;
        col = cols[idx];
        val = vals[idx];
    }
    unsigned m = __ballot_sync(0xFFFFFFFFu, slot >= 0);
    while (m) {
        int j = __ffs(m) - 1; m &= m - 1;
        int   c = __shfl_sync(0xFFFFFFFFu, col, j);
        float v = __shfl_sync(0xFFFFFFFFu, val, j);
        int   s = __shfl_sync(0xFFFFFFFFu, slot, j);
        const float* wr = &g_WqT[(size_t)c * 128];
        float* hr = &g_hsel[s * 128];
#pragma unroll
        for (int k = lane; k < 128; k += 32)
            atomicAdd(&hr[k], v * wr[k]);
    }
}

// ---- 3: reparameterize + KL ----
__global__ void k_z(const float* __restrict__ bq,
                    const float* __restrict__ eps,
                    const int* __restrict__ user) {
    int b = blockIdx.x, k = threadIdx.x;   // 64 threads
    int u = user[b];
    int s = g_map[u];
    float mu = g_hsel[s * 128 + k]      + bq[k];
    float lv = g_hsel[s * 128 + 64 + k] + bq[64 + k];
    float z  = mu + eps[u * EMB + k] * __expf(0.5f * lv);
    g_zb[b * EMB + k] = __float2bfloat16(z);
    float t = 1.f + lv - mu * mu - __expf(lv);
#pragma unroll
    for (int o = 16; o > 0; o >>= 1) t += __shfl_down_sync(0xFFFFFFFFu, t, o);
    __shared__ float sm[2];
    if ((threadIdx.x & 31) == 0) sm[threadIdx.x >> 5] = t;
    __syncthreads();
    if (threadIdx.x == 0) atomicAdd(&g_kl, sm[0] + sm[1]);
}

// ---- 4: fused decoder GEMM (bf16 HMMA) + softmax-stats epilogue ----
// Wpb tile in smem; x tile loaded coalesced 4-deep per warp (MLP), ballot-packed
// to smem bitmask in-kernel (x read ONCE, overlapped with MMA/MUFU work).
__device__ __forceinline__ void mma16816(float* d, const unsigned* a, const unsigned* b) {
    asm volatile(
        "mma.sync.aligned.m16n8k16.row.col.f32.bf16.bf16.f32 "
        "{%0,%1,%2,%3}, {%4,%5,%6,%7}, {%8,%9}, {%0,%1,%2,%3};\n"
        : "+f"(d[0]), "+f"(d[1]), "+f"(d[2]), "+f"(d[3])
        : "r"(a[0]), "r"(a[1]), "r"(a[2]), "r"(a[3]), "r"(b[0]), "r"(b[1]));
}

#define WP_STRIDE 144   // bytes per smem row: 128 data + 16 pad (bank-conflict-free)

__global__ void __launch_bounds__(256, 3)
k_gemm(const float* __restrict__ bp, const float* __restrict__ x) {
    __shared__ __align__(16) unsigned char sWp[128 * WP_STRIDE];   // 18 KB
    __shared__ __align__(16) unsigned sX[128 * 4];                 // 2 KB bitmask

    int w = threadIdx.x >> 5, lane = threadIdx.x & 31;
    int wm = w & 3, wn = w >> 2;                 // 4 warps along M, 2 along N
    int m_blk  = blockIdx.y * 128;
    int m_base = m_blk + wm * 32;                // batch rows (in-range)
    int n_blk  = blockIdx.x * 128;
    int n_base = n_blk + wn * 64;                // item cols (tail-predicated)
    int g = lane >> 2, tg = lane & 3;

    // ---- fill smem Wpb tile: rows n_blk..n_blk+127, uint4-coalesced ----
#pragma unroll
    for (int it = 0; it < 4; it++) {
        int i = it * 256 + threadIdx.x;          // 0..1023
        int row = i >> 3, off = i & 7;
        int gr = n_blk + row;
        uint4 v = make_uint4(0u, 0u, 0u, 0u);
        if (gr < NUM_ITEMS) v = *(const uint4*)&g_Wpb[(size_t)gr * 64 + off * 8];
        *(uint4*)&sWp[row * WP_STRIDE + off * 16] = v;
    }

    // ---- load + pack x tile [128 x 128] to smem bits, 4 loads in flight ----
    // warp handles rows {w, w+8, ..., w+120}; batches of 4 independent LDG.128
    // issued before any ballot so each warp keeps ~2KB outstanding.
    {
        int cb = n_blk + lane * 4;
        bool cok = (cb + 3) < NUM_ITEMS;         // tail chunk: lanes 0..15 valid
#pragma unroll
        for (int it = 0; it < 4; it++) {
            float4 v[4];
#pragma unroll
            for (int j = 0; j < 4; j++) {
                int row = it * 32 + j * 8 + w;   // 0..127
                v[j] = make_float4(0.f, 0.f, 0.f, 0.f);
                if (cok) v[j] = __ldcs((const float4*)&x[(size_t)(m_blk + row) * NUM_ITEMS + cb]);
            }
#pragma unroll
            for (int j = 0; j < 4; j++) {
                int row = it * 32 + j * 8 + w;
                unsigned b0 = __ballot_sync(0xFFFFFFFFu, v[j].x != 0.f);
                unsigned b1 = __ballot_sync(0xFFFFFFFFu, v[j].y != 0.f);
                unsigned b2 = __ballot_sync(0xFFFFFFFFu, v[j].z != 0.f);
                unsigned b3 = __ballot_sync(0xFFFFFFFFu, v[j].w != 0.f);
                if (lane == 0) *(uint4*)&sX[row * 4] = make_uint4(b0, b1, b2, b3);
            }
        }
    }

    // ---- A fragments: z tile 32(M) x 64(K), register-resident ----
    unsigned a[2][4][4];
#pragma unroll
    for (int mf = 0; mf < 2; mf++) {
        int r0 = m_base + mf * 16 + g;
#pragma unroll
        for (int kf = 0; kf < 4; kf++) {
            int kb = kf * 16 + tg * 2;
            a[mf][kf][0] = *(const unsigned*)&g_zb[(r0)     * 64 + kb];
            a[mf][kf][1] = *(const unsigned*)&g_zb[(r0 + 8) * 64 + kb];
            a[mf][kf][2] = *(const unsigned*)&g_zb[(r0)     * 64 + kb + 8];
            a[mf][kf][3] = *(const unsigned*)&g_zb[(r0 + 8) * 64 + kb + 8];
        }
    }

    __syncthreads();

    // ---- x bitmask words: loop-invariant per result row (from smem) ----
    // col c = n_base + nf*8 + tg*2 (+1); o = c - n_blk;
    // word = o&3 = 2*(tg&1) (+1 for hi col), bit t = o>>2 = 16*wn + 2*nf + (tg>>1)
    int v0   = (tg & 1) * 2;
    int tofs = wn * 16 + (tg >> 1);
    unsigned xw0[4], xw1[4];
#pragma unroll
    for (int li = 0; li < 4; li++) {
        int local = wm * 32 + (li >> 1) * 16 + (li & 1) * 8 + g;
        uint2 xv = *(const uint2*)&sX[local * 4 + v0];
        xw0[li] = xv.x; xw1[li] = xv.y;
    }

    float sexp[4] = {0, 0, 0, 0}, sdot[4] = {0, 0, 0, 0}, scnt[4] = {0, 0, 0, 0};

#pragma unroll
    for (int nf = 0; nf < 8; nf++) {
        // B fragments from smem (conflict-free LDS)
        int rloc = wn * 64 + nf * 8 + g;         // local smem row
        unsigned bf[4][2];
#pragma unroll
        for (int kf = 0; kf < 4; kf++) {
            bf[kf][0] = *(const unsigned*)&sWp[rloc * WP_STRIDE + kf * 32 + tg * 4];
            bf[kf][1] = *(const unsigned*)&sWp[rloc * WP_STRIDE + kf * 32 + tg * 4 + 16];
        }

        float d[2][4] = {{0, 0, 0, 0}, {0, 0, 0, 0}};
#pragma unroll
        for (int mf = 0; mf < 2; mf++)
#pragma unroll
            for (int kf = 0; kf < 4; kf++)
                mma16816(d[mf], a[mf][kf], bf[kf]);

        int c0 = n_base + nf * 8 + tg * 2;
        int t  = tofs + nf * 2;                  // bit position in xw words
        if (c0 < NUM_ITEMS) {
            float2 bpv = *(const float2*)&bp[c0];
#pragma unroll
            for (int mf = 0; mf < 2; mf++)
#pragma unroll
                for (int h = 0; h < 2; h++) {
                    int li = mf * 2 + h;
                    float v0f = d[mf][h * 2 + 0] + bpv.x;
                    float v1f = d[mf][h * 2 + 1] + bpv.y;
                    sexp[li] += __expf(v0f) + __expf(v1f);
                    if ((xw0[li] >> t) & 1) { sdot[li] += v0f; scnt[li] += 1.f; }
                    if ((xw1[li] >> t) & 1) { sdot[li] += v1f; scnt[li] += 1.f; }
                }
        }
    }

    // reduce across the 4 threads of each group (tg), then atomics per row
#pragma unroll
    for (int li = 0; li < 4; li++) {
        float se = sexp[li], sd = sdot[li], sc = scnt[li];
#pragma unroll
        for (int o = 1; o < 4; o <<= 1) {
            se += __shfl_xor_sync(0xFFFFFFFFu, se, o);
            sd += __shfl_xor_sync(0xFFFFFFFFu, sd, o);
            sc += __shfl_xor_sync(0xFFFFFFFFu, sc, o);
        }
        if (tg == 0) {
            int row = m_base + (li >> 1) * 16 + (li & 1) * 8 + g;
            atomicAdd(&g_sexp[row], se);
            atomicAdd(&g_sdot[row], sd);
            atomicAdd(&g_scnt[row], sc);
        }
    }
}

// ---- 5: final reduction ----
__global__ void k_final(float* __restrict__ out) {
    __shared__ float sm[256];
    float acc = 0.f;
    for (int r = threadIdx.x; r < BATCH; r += 256)
        acc += g_scnt[r] * logf(g_sexp[r]) - g_sdot[r];
    sm[threadIdx.x] = acc;
    __syncthreads();
    for (int o = 128; o > 0; o >>= 1) {
        if (threadIdx.x < o) sm[threadIdx.x] += sm[threadIdx.x + o];
        __syncthreads();
    }
    if (threadIdx.x == 0) {
        out[0] = sm[0] / (float)BATCH;
        out[1] = -0.5f * g_kl / (float)BATCH;
    }
}

extern "C" void kernel_launch(void* const* d_in, const int* in_sizes, int n_in,
                              void* d_out, int out_size) {
    const float* graph_vals = (const float*)d_in[0];
    const float* Wq         = (const float*)d_in[1];
    const float* bq         = (const float*)d_in[2];
    const float* Wp         = (const float*)d_in[3];
    const float* bp         = (const float*)d_in[4];
    const float* x          = (const float*)d_in[5];
    const float* eps        = (const float*)d_in[6];
    const int*   graph_rows = (const int*)d_in[7];
    const int*   graph_cols = (const int*)d_in[8];
    const int*   user       = (const int*)d_in[9];
    float* out = (float*)d_out;

    k_prep<<<6763, 256>>>(Wq, Wp, user);
    k_edges<<<(NNZ + 255) / 256, 256>>>(graph_vals, graph_rows, graph_cols, user);
    k_z<<<BATCH, 64>>>(bq, eps, user);
    {
        dim3 grid((NUM_ITEMS + 127) / 128, BATCH / 128);
        k_gemm<<<grid, 256>>>(bp, x);
    }
    k_final<<<1, 256>>>(out);
}